// round 2
// baseline (speedup 1.0000x reference)
#include <cuda_runtime.h>
#include <math.h>

#define NB 4
#define CC 64
#define WW 400
#define HWN (WW*WW)          // 160000

// Scratch (allocation-free rule): winner index + blend coefficients per pixel
__device__ int   g_winner[NB*HWN];
__device__ float g_a[NB*HWN];
__device__ float g_b[NB*HWN];

__global__ void reset_kernel() {
    int i = blockIdx.x * blockDim.x + threadIdx.x;
    if (i < NB*HWN) g_winner[i] = -1;
}

// Pass A: per-pixel 1x1 convs -> offsets -> scatter (atomicMax = last-write-wins), store blend coeffs
__global__ void __launch_bounds__(256) pass_a(const float* __restrict__ feat,
                                              const float* __restrict__ wc,
                                              const float* __restrict__ ws,
                                              const float* __restrict__ wp) {
    __shared__ float swc0[CC], swc1[CC], sws0[CC], sws1[CC], swp[CC];
    int t = threadIdx.x;
    if (t < CC) {
        swc0[t] = wc[t];      swc1[t] = wc[CC + t];
        sws0[t] = ws[t];      sws1[t] = ws[CC + t];
        swp[t]  = wp[t];
    }
    __syncthreads();

    int idx = blockIdx.x * blockDim.x + t;      // pixel index in [0, HWN)
    int n   = blockIdx.y;
    const float* base = feat + (size_t)n * CC * HWN + idx;

    float c0 = 0.f, c1 = 0.f, s0 = 0.f, s1 = 0.f, p = 0.f;
#pragma unroll 16
    for (int c = 0; c < CC; c++) {
        float v = __ldg(base + (size_t)c * HWN);
        c0 = fmaf(v, swc0[c], c0);
        c1 = fmaf(v, swc1[c], c1);
        s0 = fmaf(v, sws0[c], s0);
        s1 = fmaf(v, sws1[c], s1);
        p  = fmaf(v, swp[c],  p);
    }
    s0 = fmaxf(s0, 0.f);
    s1 = fmaxf(s1, 0.f);
    float pr = 1.f / (1.f + expf(-p));

    int i = idx / WW, j = idx - (idx / WW) * WW;
    // offset ch0 -> rows (h), ch1 -> cols (w); clamp max only; round half-to-even
    float th = fminf(rintf((float)i + c0 * s0), (float)(WW - 1));
    float tw = fminf(rintf((float)j + c1 * s1), (float)(WW - 1));
    int tt = (int)(th * (float)WW + tw);        // exact integers -> safe truncation
    tt %= HWN; if (tt < 0) tt += HWN;           // python-style mod (wraps negatives)

    atomicMax(&g_winner[n * HWN + tt], idx);

    float q = 1.f - pr;
    g_a[n * HWN + idx] = pr + q * q;
    g_b[n * HWN + idx] = pr * q;
}

// Pass B: gather sampled = feat[n,c, src%W, src/W] (transpose) via shared tile, blend, write.
// Block = 32x8 threads handles a 32x32 output tile over a chunk of CPB channels.
#define CPB 32
__global__ void __launch_bounds__(256) pass_b(const float* __restrict__ feat,
                                              float* __restrict__ out) {
    __shared__ float sT[32][33];
    __shared__ int   sSrc[32][32];
    __shared__ float sA[32][32];
    __shared__ float sB[32][32];

    int zc = blockIdx.z;            // n * (CC/CPB) + chunk
    int n  = zc >> 1;               // CC/CPB == 2
    int cbase = (zc & 1) * CPB;
    int i0 = blockIdx.y * 32, j0 = blockIdx.x * 32;
    int tx = threadIdx.x, ty = threadIdx.y;

    // per-pixel metadata for the tile
    for (int r = ty; r < 32; r += 8) {
        int i = i0 + r, j = j0 + tx;
        if (i < WW && j < WW) {
            int idx = i * WW + j;
            int wsrc = g_winner[n * HWN + idx];
            sSrc[r][tx] = (wsrc < 0) ? idx : wsrc;
            sA[r][tx]   = g_a[n * HWN + idx];
            sB[r][tx]   = g_b[n * HWN + idx];
        }
    }

    const float* fb = feat + (size_t)n * CC * HWN;
    float*       ob = out  + (size_t)n * CC * HWN;
    __syncthreads();

    for (int cc = 0; cc < CPB; cc++) {
        int c = cbase + cc;
        const float* fp = fb + (size_t)c * HWN;
        float*       op = ob + (size_t)c * HWN;

        // stage the transposed tile: feature rows [j0, j0+32) x cols [i0, i0+32)
        for (int r = ty; r < 32; r += 8) {
            int row = j0 + r, col = i0 + tx;
            if (row < WW && col < WW) sT[r][tx] = fp[row * WW + col];
        }
        __syncthreads();

        for (int r = ty; r < 32; r += 8) {
            int i = i0 + r, j = j0 + tx;
            if (i < WW && j < WW) {
                int src = sSrc[r][tx];
                int sh  = src / WW;           // -> x (column of feature)
                int sw  = src - sh * WW;      // -> y (row of feature)
                float s;
                int rr = sw - j0, ccol = sh - i0;
                if ((unsigned)rr < 32u && (unsigned)ccol < 32u)
                    s = sT[rr][ccol];         // identity-transpose fast path (~99.5%)
                else
                    s = __ldg(fp + (size_t)sw * WW + sh);
                float f = fp[i * WW + j];
                op[i * WW + j] = sA[r][tx] * f + sB[r][tx] * s;
            }
        }
        __syncthreads();
    }
}

extern "C" void kernel_launch(void* const* d_in, const int* in_sizes, int n_in,
                              void* d_out, int out_size) {
    const float* feat = (const float*)d_in[0];
    const float* wc   = (const float*)d_in[1];
    const float* ws   = (const float*)d_in[2];
    const float* wp   = (const float*)d_in[3];
    float* out = (float*)d_out;

    reset_kernel<<<(NB*HWN + 255) / 256, 256>>>();
    pass_a<<<dim3(HWN / 256, NB), 256>>>(feat, wc, ws, wp);
    pass_b<<<dim3((WW + 31) / 32, (WW + 31) / 32, NB * (CC / CPB)), dim3(32, 8)>>>(feat, out);
}

// round 3
// speedup vs baseline: 1.6744x; 1.6744x over previous
#include <cuda_runtime.h>
#include <math.h>

#define NB 4
#define CC 64
#define WW 400
#define HWN (WW*WW)          // 160000

// Scratch (allocation-free rule)
__device__ int   g_winner[NB*HWN];
__device__ float g_a[NB*HWN];
__device__ float g_b[NB*HWN];

__global__ void reset_kernel() {
    int i = blockIdx.x * blockDim.x + threadIdx.x;
    if (i < NB*HWN) g_winner[i] = -1;
}

// ---------------------------------------------------------------------------
// Pass A: 1x1 convs -> offsets -> scatter (atomicMax = last-write-wins),
// store blend coeffs. float4 over 4 consecutive pixels.
// ---------------------------------------------------------------------------
__global__ void __launch_bounds__(256) pass_a(const float* __restrict__ feat,
                                              const float* __restrict__ wc,
                                              const float* __restrict__ ws,
                                              const float* __restrict__ wp) {
    __shared__ float swc0[CC], swc1[CC], sws0[CC], sws1[CC], swp[CC];
    int t = threadIdx.x;
    if (t < CC) {
        swc0[t] = wc[t];      swc1[t] = wc[CC + t];
        sws0[t] = ws[t];      sws1[t] = ws[CC + t];
        swp[t]  = wp[t];
    }
    __syncthreads();

    int p4 = blockIdx.x * blockDim.x + t;        // float4 index in [0, HWN/4)
    if (p4 >= HWN/4) return;
    int n = blockIdx.y;
    const float4* f4 = (const float4*)(feat + (size_t)n * CC * HWN);

    float c0[4] = {0,0,0,0}, c1[4] = {0,0,0,0};
    float s0[4] = {0,0,0,0}, s1[4] = {0,0,0,0}, pv[4] = {0,0,0,0};
#pragma unroll 8
    for (int c = 0; c < CC; c++) {
        float4 v = __ldg(&f4[(size_t)c * (HWN/4) + p4]);
        float a0 = swc0[c], a1 = swc1[c], b0 = sws0[c], b1 = sws1[c], pw = swp[c];
        c0[0] = fmaf(v.x, a0, c0[0]); c0[1] = fmaf(v.y, a0, c0[1]);
        c0[2] = fmaf(v.z, a0, c0[2]); c0[3] = fmaf(v.w, a0, c0[3]);
        c1[0] = fmaf(v.x, a1, c1[0]); c1[1] = fmaf(v.y, a1, c1[1]);
        c1[2] = fmaf(v.z, a1, c1[2]); c1[3] = fmaf(v.w, a1, c1[3]);
        s0[0] = fmaf(v.x, b0, s0[0]); s0[1] = fmaf(v.y, b0, s0[1]);
        s0[2] = fmaf(v.z, b0, s0[2]); s0[3] = fmaf(v.w, b0, s0[3]);
        s1[0] = fmaf(v.x, b1, s1[0]); s1[1] = fmaf(v.y, b1, s1[1]);
        s1[2] = fmaf(v.z, b1, s1[2]); s1[3] = fmaf(v.w, b1, s1[3]);
        pv[0] = fmaf(v.x, pw, pv[0]); pv[1] = fmaf(v.y, pw, pv[1]);
        pv[2] = fmaf(v.z, pw, pv[2]); pv[3] = fmaf(v.w, pw, pv[3]);
    }

    float4 av, bv;
    float* avp = &av.x; float* bvp = &bv.x;
#pragma unroll
    for (int m = 0; m < 4; m++) {
        int idx = p4 * 4 + m;
        float st0 = fmaxf(s0[m], 0.f), st1 = fmaxf(s1[m], 0.f);
        float pr = 1.f / (1.f + expf(-pv[m]));
        int i = idx / WW, j = idx - (idx / WW) * WW;
        float th = fminf(rintf((float)i + c0[m] * st0), (float)(WW - 1));
        float tw = fminf(rintf((float)j + c1[m] * st1), (float)(WW - 1));
        int tt = (int)(th * (float)WW + tw);
        tt %= HWN; if (tt < 0) tt += HWN;        // python-style mod
        atomicMax(&g_winner[n * HWN + tt], idx);
        float q = 1.f - pr;
        avp[m] = pr + q * q;
        bvp[m] = pr * q;
    }
    ((float4*)g_a)[(size_t)n * (HWN/4) + p4] = av;
    ((float4*)g_b)[(size_t)n * (HWN/4) + p4] = bv;
}

// ---------------------------------------------------------------------------
// Pass B: gather sampled = feat[n,c, src%W, src/W] (transpose) via staged
// shared tiles, blend, write. 32x32 spatial tile, NSTG=4 channels per barrier
// pair, float4 global IO, precomputed gather offsets.
// ---------------------------------------------------------------------------
#define TS   32
#define NSTG 4
#define CPB  32
#define FAST_TAG 0x40000000

__global__ void __launch_bounds__(256) pass_b(const float* __restrict__ feat,
                                              float* __restrict__ out) {
    __shared__ float sT[NSTG][TS][33];
    __shared__ int   sG[TS][TS];
    __shared__ float sA2[TS][TS];
    __shared__ float sB2[TS][TS];

    int zc = blockIdx.z;                 // n*(CC/CPB) + chunk
    int n  = zc >> 1;                    // CC/CPB == 2
    int cbase = (zc & 1) * CPB;
    int i0 = blockIdx.y * TS, j0 = blockIdx.x * TS;
    int tid = threadIdx.x;

    // per-pixel metadata, once per tile
    for (int p = tid; p < TS*TS; p += 256) {
        int r = p >> 5, c = p & 31;
        int i = i0 + r, j = j0 + c;
        if (i < WW && j < WW) {
            int idx = i * WW + j;
            int wsrc = g_winner[n * HWN + idx];
            int src  = (wsrc < 0) ? idx : wsrc;
            int sh = src / WW;            // -> column of feature
            int sw = src - sh * WW;       // -> row of feature
            int lr = sw - j0, lc = sh - i0;
            sG[r][c] = ((unsigned)lr < (unsigned)TS && (unsigned)lc < (unsigned)TS)
                       ? (lr * 33 + lc)
                       : (FAST_TAG | (sw * WW + sh));
            sA2[r][c] = g_a[n * HWN + idx];
            sB2[r][c] = g_b[n * HWN + idx];
        }
    }

    const float* fb = feat + (size_t)n * CC * HWN;
    float*       ob = out  + (size_t)n * CC * HWN;

    int trow = tid >> 3, tq = tid & 7;   // stage/compute mapping: 32 rows x 8 quads
    __syncthreads();

    for (int g0 = 0; g0 < CPB; g0 += NSTG) {
        // stage NSTG transposed tiles: feature rows [j0,j0+32) x cols [i0,i0+32)
#pragma unroll
        for (int s = 0; s < NSTG; s++) {
            const float* fp = fb + (size_t)(cbase + g0 + s) * HWN;
            int row = j0 + trow, col = i0 + tq * 4;
            if (row < WW) {
                if (col + 3 < WW) {
                    float4 v = __ldg((const float4*)(fp + row * WW + col));
                    sT[s][trow][tq*4+0] = v.x; sT[s][trow][tq*4+1] = v.y;
                    sT[s][trow][tq*4+2] = v.z; sT[s][trow][tq*4+3] = v.w;
                } else {
#pragma unroll
                    for (int k = 0; k < 4; k++)
                        if (col + k < WW) sT[s][trow][tq*4+k] = fp[row * WW + col + k];
                }
            }
        }
        __syncthreads();

        // compute NSTG channels
        int i = i0 + trow;
        int jb = j0 + tq * 4;
        if (i < WW && jb < WW) {
            bool full = (jb + 3 < WW);
#pragma unroll
            for (int s = 0; s < NSTG; s++) {
                const float* fp = fb + (size_t)(cbase + g0 + s) * HWN;
                float*       op = ob + (size_t)(cbase + g0 + s) * HWN;
                const float* stc = &sT[s][0][0];
                if (full) {
                    float4 f = __ldg((const float4*)(fp + i * WW + jb));
                    float4 o;
                    float* fpx = &f.x; float* opx = &o.x;
#pragma unroll
                    for (int m = 0; m < 4; m++) {
                        int gidx = sG[trow][tq*4+m];
                        float sval = (gidx & FAST_TAG)
                                   ? __ldg(fp + (gidx & (FAST_TAG-1)))
                                   : stc[gidx];
                        opx[m] = sA2[trow][tq*4+m] * fpx[m] + sB2[trow][tq*4+m] * sval;
                    }
                    *((float4*)(op + i * WW + jb)) = o;
                } else {
#pragma unroll
                    for (int m = 0; m < 4; m++) {
                        if (jb + m < WW) {
                            int gidx = sG[trow][tq*4+m];
                            float sval = (gidx & FAST_TAG)
                                       ? __ldg(fp + (gidx & (FAST_TAG-1)))
                                       : stc[gidx];
                            op[i * WW + jb + m] = sA2[trow][tq*4+m] * fp[i * WW + jb + m]
                                                + sB2[trow][tq*4+m] * sval;
                        }
                    }
                }
            }
        }
        __syncthreads();
    }
}

extern "C" void kernel_launch(void* const* d_in, const int* in_sizes, int n_in,
                              void* d_out, int out_size) {
    const float* feat = (const float*)d_in[0];
    const float* wc   = (const float*)d_in[1];
    const float* ws   = (const float*)d_in[2];
    const float* wp   = (const float*)d_in[3];
    float* out = (float*)d_out;

    reset_kernel<<<(NB*HWN + 255) / 256, 256>>>();
    pass_a<<<dim3((HWN/4 + 255) / 256, NB), 256>>>(feat, wc, ws, wp);
    pass_b<<<dim3((WW + TS - 1) / TS, (WW + TS - 1) / TS, NB * (CC / CPB)),
             256>>>(feat, out);
}

// round 4
// speedup vs baseline: 2.0004x; 1.1947x over previous
#include <cuda_runtime.h>
#include <math.h>

#define NB 4
#define CC 64
#define WW 400
#define HWN (WW*WW)          // 160000
#define TS 32
#define NSTG 4
#define FAST_TAG 0x40000000

// Scratch (allocation-free rule). Zero-initialized at module load; pass_b
// self-resets g_winner to 0 after consuming it, so every kernel_launch call
// (correctness run + each graph replay) sees the same initial state.
__device__ int   g_winner[NB*HWN];   // stores winner_idx+1; 0 = no winner
__device__ float g_a[NB*HWN];
__device__ float g_b[NB*HWN];

// ---------------------------------------------------------------------------
// Pass A: 1x1 convs -> offsets -> scatter (atomicMax(idx+1) = last-write-wins),
// store blend coeffs. float4 over 4 consecutive pixels.
// ---------------------------------------------------------------------------
__global__ void __launch_bounds__(256) pass_a(const float* __restrict__ feat,
                                              const float* __restrict__ wc,
                                              const float* __restrict__ ws,
                                              const float* __restrict__ wp) {
    __shared__ float swc0[CC], swc1[CC], sws0[CC], sws1[CC], swp[CC];
    int t = threadIdx.x;
    if (t < CC) {
        swc0[t] = wc[t];      swc1[t] = wc[CC + t];
        sws0[t] = ws[t];      sws1[t] = ws[CC + t];
        swp[t]  = wp[t];
    }
    __syncthreads();

    int p4 = blockIdx.x * blockDim.x + t;        // float4 index in [0, HWN/4)
    if (p4 >= HWN/4) return;
    int n = blockIdx.y;
    const float4* f4 = (const float4*)(feat + (size_t)n * CC * HWN);

    float c0[4] = {0,0,0,0}, c1[4] = {0,0,0,0};
    float s0[4] = {0,0,0,0}, s1[4] = {0,0,0,0}, pv[4] = {0,0,0,0};
#pragma unroll 8
    for (int c = 0; c < CC; c++) {
        float4 v = __ldg(&f4[(size_t)c * (HWN/4) + p4]);
        float a0 = swc0[c], a1 = swc1[c], b0 = sws0[c], b1 = sws1[c], pw = swp[c];
        c0[0] = fmaf(v.x, a0, c0[0]); c0[1] = fmaf(v.y, a0, c0[1]);
        c0[2] = fmaf(v.z, a0, c0[2]); c0[3] = fmaf(v.w, a0, c0[3]);
        c1[0] = fmaf(v.x, a1, c1[0]); c1[1] = fmaf(v.y, a1, c1[1]);
        c1[2] = fmaf(v.z, a1, c1[2]); c1[3] = fmaf(v.w, a1, c1[3]);
        s0[0] = fmaf(v.x, b0, s0[0]); s0[1] = fmaf(v.y, b0, s0[1]);
        s0[2] = fmaf(v.z, b0, s0[2]); s0[3] = fmaf(v.w, b0, s0[3]);
        s1[0] = fmaf(v.x, b1, s1[0]); s1[1] = fmaf(v.y, b1, s1[1]);
        s1[2] = fmaf(v.z, b1, s1[2]); s1[3] = fmaf(v.w, b1, s1[3]);
        pv[0] = fmaf(v.x, pw, pv[0]); pv[1] = fmaf(v.y, pw, pv[1]);
        pv[2] = fmaf(v.z, pw, pv[2]); pv[3] = fmaf(v.w, pw, pv[3]);
    }

    float4 av, bv;
    float* avp = &av.x; float* bvp = &bv.x;
#pragma unroll
    for (int m = 0; m < 4; m++) {
        int idx = p4 * 4 + m;
        float st0 = fmaxf(s0[m], 0.f), st1 = fmaxf(s1[m], 0.f);
        float pr = 1.f / (1.f + expf(-pv[m]));
        int i = idx / WW, j = idx - (idx / WW) * WW;
        float th = fminf(rintf((float)i + c0[m] * st0), (float)(WW - 1));
        float tw = fminf(rintf((float)j + c1[m] * st1), (float)(WW - 1));
        int tt = (int)(th * (float)WW + tw);
        tt %= HWN; if (tt < 0) tt += HWN;        // python-style mod
        atomicMax(&g_winner[n * HWN + tt], idx + 1);
        float q = 1.f - pr;
        avp[m] = pr + q * q;
        bvp[m] = pr * q;
    }
    ((float4*)g_a)[(size_t)n * (HWN/4) + p4] = av;
    ((float4*)g_b)[(size_t)n * (HWN/4) + p4] = bv;
}

// ---------------------------------------------------------------------------
// Pass B: mirror-tile pairs. Block (bx,by), by<=bx, owns output tiles
//   A: rows [aR,aR+ah) x cols [aC,aC+aw)   (aR=by*32, aC=bx*32)
//   B: rows [aC,aC+aw) x cols [aR,aR+ah)   (mirror; skipped when diagonal)
// Staged tile A doubles as f for A-outputs and gather source for B-outputs
// (and vice versa), since sampled = feat[src%W][src/W] is the near-transpose.
// All 64 channels per block; metadata held in registers; winner self-reset.
// ---------------------------------------------------------------------------
__global__ void __launch_bounds__(256) pass_b(const float* __restrict__ feat,
                                              float* __restrict__ out) {
    __shared__ float sTA[NSTG][TS][33];
    __shared__ float sTB[NSTG][TS][33];

    int bx = blockIdx.x, by = blockIdx.y;
    if (by > bx) return;
    bool diag = (bx == by);
    int n = blockIdx.z;

    int aR = by * TS, aC = bx * TS;
    int ah = min(TS, WW - aR), aw = min(TS, WW - aC);   // 32 or 16 (mult of 4)

    int tid = threadIdx.x;
    int trow = tid >> 3, tc0 = (tid & 7) * 4;

    const float* fb = feat + (size_t)n * CC * HWN;
    float*       ob = out  + (size_t)n * CC * HWN;
    int*         wn = g_winner + n * HWN;
    const float* ga = g_a + n * HWN;
    const float* gb = g_b + n * HWN;

    // ---- metadata for this thread's 4 A-pixels (registers) ----
    bool aval = (trow < ah) && (tc0 < aw);
    int gA[4]; float4 cAa, cAb;
    if (aval) {
        int idx = (aR + trow) * WW + aC + tc0;
        int4 w4 = *(const int4*)(wn + idx);
        cAa = *(const float4*)(ga + idx);
        cAb = *(const float4*)(gb + idx);
        *(int4*)(wn + idx) = make_int4(0, 0, 0, 0);     // self-reset
        int wv[4] = {w4.x, w4.y, w4.z, w4.w};
#pragma unroll
        for (int m = 0; m < 4; m++) {
            int src = (wv[m] > 0) ? (wv[m] - 1) : (idx + m);
            int sh = src / WW, sw = src - sh * WW;       // sampled = feat[sw][sh]
            int lr = sw - aC, lc = sh - aR;              // into B region
            gA[m] = ((unsigned)lr < (unsigned)aw && (unsigned)lc < (unsigned)ah)
                    ? (lr * 33 + lc)
                    : (FAST_TAG | (sw * WW + sh));
        }
    }
    // ---- metadata for this thread's 4 B-pixels ----
    bool bval = (!diag) && (trow < aw) && (tc0 < ah);
    int gB[4]; float4 cBa, cBb;
    if (bval) {
        int idx = (aC + trow) * WW + aR + tc0;
        int4 w4 = *(const int4*)(wn + idx);
        cBa = *(const float4*)(ga + idx);
        cBb = *(const float4*)(gb + idx);
        *(int4*)(wn + idx) = make_int4(0, 0, 0, 0);
        int wv[4] = {w4.x, w4.y, w4.z, w4.w};
#pragma unroll
        for (int m = 0; m < 4; m++) {
            int src = (wv[m] > 0) ? (wv[m] - 1) : (idx + m);
            int sh = src / WW, sw = src - sh * WW;
            int lr = sw - aR, lc = sh - aC;              // into A region
            gB[m] = ((unsigned)lr < (unsigned)ah && (unsigned)lc < (unsigned)aw)
                    ? (lr * 33 + lc)
                    : (FAST_TAG | (sw * WW + sh));
        }
    }

    for (int g0 = 0; g0 < CC; g0 += NSTG) {
        // ---- stage NSTG channels of A (and B) ----
#pragma unroll
        for (int s = 0; s < NSTG; s++) {
            const float* fp = fb + (size_t)(g0 + s) * HWN;
            if (aval) {
                float4 v = __ldg((const float4*)(fp + (aR + trow) * WW + aC + tc0));
                sTA[s][trow][tc0+0] = v.x; sTA[s][trow][tc0+1] = v.y;
                sTA[s][trow][tc0+2] = v.z; sTA[s][trow][tc0+3] = v.w;
            }
            if (bval) {
                float4 v = __ldg((const float4*)(fp + (aC + trow) * WW + aR + tc0));
                sTB[s][trow][tc0+0] = v.x; sTB[s][trow][tc0+1] = v.y;
                sTB[s][trow][tc0+2] = v.z; sTB[s][trow][tc0+3] = v.w;
            }
        }
        __syncthreads();

        // ---- compute + store ----
#pragma unroll
        for (int s = 0; s < NSTG; s++) {
            const float* fp = fb + (size_t)(g0 + s) * HWN;
            float*       op = ob + (size_t)(g0 + s) * HWN;
            if (aval) {
                const float* gsrc = diag ? &sTA[s][0][0] : &sTB[s][0][0];
                const float* frow = &sTA[s][trow][tc0];
                float4 o;
                float* ox = &o.x;
                const float* ca = &cAa.x; const float* cb = &cAb.x;
#pragma unroll
                for (int m = 0; m < 4; m++) {
                    int gi = gA[m];
                    float sval = (gi & FAST_TAG) ? __ldg(fp + (gi & (FAST_TAG-1)))
                                                 : gsrc[gi];
                    ox[m] = ca[m] * frow[m] + cb[m] * sval;
                }
                *(float4*)(op + (aR + trow) * WW + aC + tc0) = o;
            }
            if (bval) {
                const float* gsrc = &sTA[s][0][0];
                const float* frow = &sTB[s][trow][tc0];
                float4 o;
                float* ox = &o.x;
                const float* ca = &cBa.x; const float* cb = &cBb.x;
#pragma unroll
                for (int m = 0; m < 4; m++) {
                    int gi = gB[m];
                    float sval = (gi & FAST_TAG) ? __ldg(fp + (gi & (FAST_TAG-1)))
                                                 : gsrc[gi];
                    ox[m] = ca[m] * frow[m] + cb[m] * sval;
                }
                *(float4*)(op + (aC + trow) * WW + aR + tc0) = o;
            }
        }
        __syncthreads();
    }
}

extern "C" void kernel_launch(void* const* d_in, const int* in_sizes, int n_in,
                              void* d_out, int out_size) {
    const float* feat = (const float*)d_in[0];
    const float* wc   = (const float*)d_in[1];
    const float* ws   = (const float*)d_in[2];
    const float* wp   = (const float*)d_in[3];
    float* out = (float*)d_out;

    pass_a<<<dim3((HWN/4 + 255) / 256, NB), 256>>>(feat, wc, ws, wp);
    pass_b<<<dim3((WW + TS - 1) / TS, (WW + TS - 1) / TS, NB), 256>>>(feat, out);
}

// round 5
// speedup vs baseline: 2.4681x; 1.2338x over previous
#include <cuda_runtime.h>
#include <math.h>

#define NB 4
#define CC 64
#define WW 400
#define HWN (WW*WW)          // 160000
#define TS 32
#define CPB 32               // channels per pass_b block (z-split 2)
#define NSTG 2               // channels per pipeline stage-group
#define NGRP (CPB/NSTG)      // 16
#define FAST_TAG 0x40000000

// Scratch (allocation-free rule). Zero-init at load; reset_kernel restores
// g_winner to zeros after pass_b consumes it (deterministic per replay).
__device__ int   g_winner[NB*HWN];   // winner_idx+1; 0 = no winner
__device__ float g_a[NB*HWN];
__device__ float g_b[NB*HWN];

__global__ void __launch_bounds__(256) reset_kernel() {
    int i = blockIdx.x * blockDim.x + threadIdx.x;   // 625*256 = NB*HWN/4
    ((int4*)g_winner)[i] = make_int4(0, 0, 0, 0);
}

__device__ __forceinline__ void cp16(void* smem, const void* g) {
    unsigned s = (unsigned)__cvta_generic_to_shared(smem);
    asm volatile("cp.async.cg.shared.global [%0], [%1], 16;" :: "r"(s), "l"(g));
}
// swizzled scalar offset within a 32x32 tile (float units)
__device__ __forceinline__ int swz(int r, int c) {
    return r * 32 + ((((c >> 2) ^ (r >> 2)) & 7) << 2) + (c & 3);
}

// ---------------------------------------------------------------------------
// Pass A: 1x1 convs -> offsets -> scatter (atomicMax(idx+1) = last-write-wins),
// store blend coeffs. float4 over 4 consecutive pixels.
// ---------------------------------------------------------------------------
__global__ void __launch_bounds__(256) pass_a(const float* __restrict__ feat,
                                              const float* __restrict__ wc,
                                              const float* __restrict__ ws,
                                              const float* __restrict__ wp) {
    __shared__ float swc0[CC], swc1[CC], sws0[CC], sws1[CC], swp[CC];
    int t = threadIdx.x;
    if (t < CC) {
        swc0[t] = wc[t];      swc1[t] = wc[CC + t];
        sws0[t] = ws[t];      sws1[t] = ws[CC + t];
        swp[t]  = wp[t];
    }
    __syncthreads();

    int p4 = blockIdx.x * blockDim.x + t;
    if (p4 >= HWN/4) return;
    int n = blockIdx.y;
    const float4* f4 = (const float4*)(feat + (size_t)n * CC * HWN);

    float c0[4] = {0,0,0,0}, c1[4] = {0,0,0,0};
    float s0[4] = {0,0,0,0}, s1[4] = {0,0,0,0}, pv[4] = {0,0,0,0};
#pragma unroll 8
    for (int c = 0; c < CC; c++) {
        float4 v = __ldg(&f4[(size_t)c * (HWN/4) + p4]);
        float a0 = swc0[c], a1 = swc1[c], b0 = sws0[c], b1 = sws1[c], pw = swp[c];
        c0[0] = fmaf(v.x, a0, c0[0]); c0[1] = fmaf(v.y, a0, c0[1]);
        c0[2] = fmaf(v.z, a0, c0[2]); c0[3] = fmaf(v.w, a0, c0[3]);
        c1[0] = fmaf(v.x, a1, c1[0]); c1[1] = fmaf(v.y, a1, c1[1]);
        c1[2] = fmaf(v.z, a1, c1[2]); c1[3] = fmaf(v.w, a1, c1[3]);
        s0[0] = fmaf(v.x, b0, s0[0]); s0[1] = fmaf(v.y, b0, s0[1]);
        s0[2] = fmaf(v.z, b0, s0[2]); s0[3] = fmaf(v.w, b0, s0[3]);
        s1[0] = fmaf(v.x, b1, s1[0]); s1[1] = fmaf(v.y, b1, s1[1]);
        s1[2] = fmaf(v.z, b1, s1[2]); s1[3] = fmaf(v.w, b1, s1[3]);
        pv[0] = fmaf(v.x, pw, pv[0]); pv[1] = fmaf(v.y, pw, pv[1]);
        pv[2] = fmaf(v.z, pw, pv[2]); pv[3] = fmaf(v.w, pw, pv[3]);
    }

    float4 av, bv;
    float* avp = &av.x; float* bvp = &bv.x;
#pragma unroll
    for (int m = 0; m < 4; m++) {
        int idx = p4 * 4 + m;
        float st0 = fmaxf(s0[m], 0.f), st1 = fmaxf(s1[m], 0.f);
        float pr = 1.f / (1.f + expf(-pv[m]));
        int i = idx / WW, j = idx - (idx / WW) * WW;
        float th = fminf(rintf((float)i + c0[m] * st0), (float)(WW - 1));
        float tw = fminf(rintf((float)j + c1[m] * st1), (float)(WW - 1));
        int tt = (int)(th * (float)WW + tw);
        tt %= HWN; if (tt < 0) tt += HWN;        // python-style mod
        atomicMax(&g_winner[n * HWN + tt], idx + 1);
        float q = 1.f - pr;
        avp[m] = pr + q * q;
        bvp[m] = pr * q;
    }
    ((float4*)g_a)[(size_t)n * (HWN/4) + p4] = av;
    ((float4*)g_b)[(size_t)n * (HWN/4) + p4] = bv;
}

// ---------------------------------------------------------------------------
// Pass B: mirror-tile pairs + cp.async double-buffered channel pipeline.
// Block (bx,by), by<=bx, z = n*2 + channel-half. Output tiles:
//   A: rows [aR..) x cols [aC..)    B: mirror (skipped when diagonal)
// Staged tile A is f-source for A and gather source for B (and vice versa).
// Tiles stored with float4-slot XOR swizzle: 16B-aligned for cp.async AND
// conflict-free for both row-major f-reads and transpose-pattern gathers.
// ---------------------------------------------------------------------------
__global__ void __launch_bounds__(256) pass_b(const float* __restrict__ feat,
                                              float* __restrict__ out) {
    __shared__ float sbuf[2][NSTG][2][TS*TS];   // [buf][stage-ch][tile A/B][swizzled]

    int bx = blockIdx.x, by = blockIdx.y;
    if (by > bx) return;
    bool diag = (bx == by);
    int zc = blockIdx.z;
    int n = zc >> 1;
    int cbase = (zc & 1) * CPB;

    int aR = by * TS, aC = bx * TS;
    int ah = min(TS, WW - aR), aw = min(TS, WW - aC);   // 32 or 16

    int tid = threadIdx.x;
    int trow = tid >> 3, tq = tid & 7, tc0 = tq * 4;
    int slotoff = trow * 32 + ((tq ^ (trow >> 2)) & 7) * 4;  // this thread's staged float4

    const float* fb = feat + (size_t)n * CC * HWN;
    float*       ob = out  + (size_t)n * CC * HWN;
    const int*   wn = g_winner + n * HWN;
    const float* ga = g_a + n * HWN;
    const float* gb = g_b + n * HWN;

    bool aval = (trow < ah) && (tc0 < aw);
    bool bval = (!diag) && (trow < aw) && (tc0 < ah);

    // ---- metadata (registers), read-only ----
    int gA[4]; float4 cAa, cAb;
    if (aval) {
        int idx = (aR + trow) * WW + aC + tc0;
        int4 w4 = *(const int4*)(wn + idx);
        cAa = *(const float4*)(ga + idx);
        cAb = *(const float4*)(gb + idx);
        int wv[4] = {w4.x, w4.y, w4.z, w4.w};
#pragma unroll
        for (int m = 0; m < 4; m++) {
            int src = (wv[m] > 0) ? (wv[m] - 1) : (idx + m);
            int sh = src / WW, sw = src - sh * WW;       // sampled = feat[sw][sh]
            int lr = sw - aC, lc = sh - aR;              // into B region
            gA[m] = ((unsigned)lr < (unsigned)aw && (unsigned)lc < (unsigned)ah)
                    ? swz(lr, lc)
                    : (FAST_TAG | (sw * WW + sh));
        }
    }
    int gB[4]; float4 cBa, cBb;
    if (bval) {
        int idx = (aC + trow) * WW + aR + tc0;
        int4 w4 = *(const int4*)(wn + idx);
        cBa = *(const float4*)(ga + idx);
        cBb = *(const float4*)(gb + idx);
        int wv[4] = {w4.x, w4.y, w4.z, w4.w};
#pragma unroll
        for (int m = 0; m < 4; m++) {
            int src = (wv[m] > 0) ? (wv[m] - 1) : (idx + m);
            int sh = src / WW, sw = src - sh * WW;
            int lr = sw - aR, lc = sh - aC;              // into A region
            gB[m] = ((unsigned)lr < (unsigned)ah && (unsigned)lc < (unsigned)aw)
                    ? swz(lr, lc)
                    : (FAST_TAG | (sw * WW + sh));
        }
    }

    // ---- stage lambda: group g -> buffer b ----
    auto stage = [&](int g, int b) {
#pragma unroll
        for (int s = 0; s < NSTG; s++) {
            const float* fp = fb + (size_t)(cbase + g * NSTG + s) * HWN;
            if (aval) cp16(&sbuf[b][s][0][slotoff], fp + (aR + trow) * WW + aC + tc0);
            if (bval) cp16(&sbuf[b][s][1][slotoff], fp + (aC + trow) * WW + aR + tc0);
        }
        asm volatile("cp.async.commit_group;");
    };

    stage(0, 0);
    stage(1, 1);

    for (int g = 0; g < NGRP; g++) {
        int b = g & 1;
        if (g < NGRP - 1) asm volatile("cp.async.wait_group 1;");
        else              asm volatile("cp.async.wait_group 0;");
        __syncthreads();

#pragma unroll
        for (int s = 0; s < NSTG; s++) {
            int ch = cbase + g * NSTG + s;
            const float* fp = fb + (size_t)ch * HWN;
            float*       op = ob + (size_t)ch * HWN;
            const float* tA = sbuf[b][s][0];
            const float* tB = sbuf[b][s][1];
            if (aval) {
                const float* gsrc = diag ? tA : tB;
                float4 f = *(const float4*)(tA + slotoff);
                const float* fx = &f.x;
                const float* ca = &cAa.x; const float* cb = &cAb.x;
                float4 o; float* ox = &o.x;
#pragma unroll
                for (int m = 0; m < 4; m++) {
                    int gi = gA[m];
                    float sval = (gi & FAST_TAG) ? __ldg(fp + (gi & (FAST_TAG-1)))
                                                 : gsrc[gi];
                    ox[m] = ca[m] * fx[m] + cb[m] * sval;
                }
                *(float4*)(op + (aR + trow) * WW + aC + tc0) = o;
            }
            if (bval) {
                float4 f = *(const float4*)(tB + slotoff);
                const float* fx = &f.x;
                const float* ca = &cBa.x; const float* cb = &cBb.x;
                float4 o; float* ox = &o.x;
#pragma unroll
                for (int m = 0; m < 4; m++) {
                    int gi = gB[m];
                    float sval = (gi & FAST_TAG) ? __ldg(fp + (gi & (FAST_TAG-1)))
                                                 : tA[gi];
                    ox[m] = ca[m] * fx[m] + cb[m] * sval;
                }
                *(float4*)(op + (aC + trow) * WW + aR + tc0) = o;
            }
        }
        __syncthreads();
        if (g + 2 < NGRP) stage(g + 2, b);
    }
}

extern "C" void kernel_launch(void* const* d_in, const int* in_sizes, int n_in,
                              void* d_out, int out_size) {
    const float* feat = (const float*)d_in[0];
    const float* wc   = (const float*)d_in[1];
    const float* ws   = (const float*)d_in[2];
    const float* wp   = (const float*)d_in[3];
    float* out = (float*)d_out;

    pass_a<<<dim3((HWN/4 + 255) / 256, NB), 256>>>(feat, wc, ws, wp);
    pass_b<<<dim3((WW + TS - 1) / TS, (WW + TS - 1) / TS, NB * 2), 256>>>(feat, out);
    reset_kernel<<<NB*HWN/4/256, 256>>>();
}